// round 1
// baseline (speedup 1.0000x reference)
#include <cuda_runtime.h>
#include <math.h>

#define BATCH 4096

// Intermediate activation scratch (allocation-free: __device__ globals).
__device__ float g_h1[(size_t)BATCH * 10 * 19 * 19];   // ~59 MB
__device__ float g_h2[(size_t)BATCH * 20 * 10 * 10];   // ~33 MB

// ---------------------------------------------------------------------------
// conv1: in [1,28,28] -> relu -> out [10,19,19], kernel 10x10
// One block per image. Thread = (oc, output row). 190 active of 192.
// Per ky: stage full 28-wide input row in registers, reuse across kx/ox.
// ---------------------------------------------------------------------------
__global__ __launch_bounds__(192) void conv1_kernel(
    const float* __restrict__ x, const float* __restrict__ w1,
    const float* __restrict__ b1)
{
    __shared__ float s_in[784];    // 28*28
    __shared__ float s_w[1000];    // 10*100
    const int img = blockIdx.x;
    const int tid = threadIdx.x;

    const float* xin = x + (size_t)img * 784;
    for (int i = tid; i < 784; i += 192) s_in[i] = xin[i];
    for (int i = tid; i < 1000; i += 192) s_w[i] = w1[i];
    __syncthreads();

    if (tid < 190) {
        const int oc = tid / 19;   // 0..9
        const int oy = tid % 19;   // 0..18
        float acc[19];
        const float bias = __ldg(&b1[oc]);
        #pragma unroll
        for (int q = 0; q < 19; q++) acc[q] = bias;

        for (int ky = 0; ky < 10; ky++) {
            float iv[28];
            const float* rp = &s_in[(oy + ky) * 28];
            #pragma unroll
            for (int j = 0; j < 28; j++) iv[j] = rp[j];
            const float* wr = &s_w[oc * 100 + ky * 10];
            #pragma unroll
            for (int kx = 0; kx < 10; kx++) {
                const float wv = wr[kx];
                #pragma unroll
                for (int q = 0; q < 19; q++) acc[q] = fmaf(iv[q + kx], wv, acc[q]);
            }
        }
        float* op = &g_h1[(size_t)img * 3610 + oc * 361 + oy * 19];
        #pragma unroll
        for (int q = 0; q < 19; q++) op[q] = fmaxf(acc[q], 0.0f);
    }
}

// ---------------------------------------------------------------------------
// conv2: in [10,19,19] -> relu -> out [20,10,10], kernel 10x10
// One block per image. Thread = (2 output channels, 1 output row of 10).
// 100 active of 128. Loop input channels; per channel stage the plane +
// weight slice in smem. Per ky: stage full 19-wide input row in regs.
// LDS:FFMA ~ 0.2; input row loads conflict-free (19*oy mod 32 distinct).
// ---------------------------------------------------------------------------
__global__ __launch_bounds__(128) void conv2_kernel(
    const float* __restrict__ w2, const float* __restrict__ b2)
{
    __shared__ float s_in[361];    // 19*19, one channel
    __shared__ float s_w[2000];    // 20 oc * 100, one input channel slice
    const int img = blockIdx.x;
    const int tid = threadIdx.x;
    const bool act = tid < 100;
    const int ocg = tid / 10;      // 0..9  -> oc0 = 2*ocg
    const int oy  = tid % 10;      // output row
    const int oc0 = ocg * 2;

    float acc0[10], acc1[10];
    if (act) {
        const float b0v = __ldg(&b2[oc0]);
        const float b1v = __ldg(&b2[oc0 + 1]);
        #pragma unroll
        for (int q = 0; q < 10; q++) { acc0[q] = b0v; acc1[q] = b1v; }
    }

    const float* h1p = g_h1 + (size_t)img * 3610;
    for (int c = 0; c < 10; c++) {
        __syncthreads();
        for (int i = tid; i < 361; i += 128) s_in[i] = h1p[c * 361 + i];
        for (int i = tid; i < 2000; i += 128) {
            const int oc = i / 100, k = i % 100;
            s_w[i] = w2[oc * 1000 + c * 100 + k];
        }
        __syncthreads();

        if (act) {
            for (int ky = 0; ky < 10; ky++) {
                float iv[19];
                const float* rp = &s_in[(oy + ky) * 19];
                #pragma unroll
                for (int j = 0; j < 19; j++) iv[j] = rp[j];
                const float* w0p = &s_w[oc0 * 100 + ky * 10];
                const float* w1p = w0p + 100;
                #pragma unroll
                for (int kx = 0; kx < 10; kx++) {
                    const float w0 = w0p[kx];
                    const float w1v = w1p[kx];
                    #pragma unroll
                    for (int q = 0; q < 10; q++) {
                        acc0[q] = fmaf(iv[q + kx], w0,  acc0[q]);
                        acc1[q] = fmaf(iv[q + kx], w1v, acc1[q]);
                    }
                }
            }
        }
    }

    if (act) {
        float* op = g_h2 + (size_t)img * 2000 + oc0 * 100 + oy * 10;
        #pragma unroll
        for (int q = 0; q < 10; q++) {
            op[q]       = fmaxf(acc0[q], 0.0f);
            op[100 + q] = fmaxf(acc1[q], 0.0f);
        }
    }
}

// ---------------------------------------------------------------------------
// conv3 + FC: in [20,10,10] -> relu conv [20,6,6] (kernel 5x5) -> flatten 720
//             -> out[10] = h @ wf^T + bf
// One block per image, 128 threads. Conv thread = (oc, output row), 120 active.
// Conv result kept in smem; FC done by all 128 threads with strided partials
// + warp-shuffle reduction.
// ---------------------------------------------------------------------------
__global__ __launch_bounds__(128) void conv3_fc_kernel(
    const float* __restrict__ w3, const float* __restrict__ b3,
    const float* __restrict__ wf, const float* __restrict__ bf,
    float* __restrict__ out)
{
    __shared__ float s_in[100];    // one input channel plane 10x10
    __shared__ float s_w[500];     // 20 oc * 25, one input channel slice
    __shared__ float s_h[720];     // conv3 relu output, flattened (oc*36 + oy*6 + ox)
    __shared__ float s_wf[7200];   // FC weights [10][720]
    __shared__ float s_red[40];    // per-warp FC partials

    const int img = blockIdx.x;
    const int tid = threadIdx.x;

    for (int i = tid; i < 7200; i += 128) s_wf[i] = wf[i];

    const bool act = tid < 120;
    const int oc = tid / 6;        // 0..19
    const int oy = tid % 6;        // 0..5
    float acc[6];
    if (act) {
        const float bv = __ldg(&b3[oc]);
        #pragma unroll
        for (int q = 0; q < 6; q++) acc[q] = bv;
    }

    const float* h2p = g_h2 + (size_t)img * 2000;
    for (int c = 0; c < 20; c++) {
        __syncthreads();
        if (tid < 100) s_in[tid] = h2p[c * 100 + tid];
        for (int i = tid; i < 500; i += 128) {
            const int o = i / 25, k = i % 25;
            s_w[i] = w3[o * 500 + c * 25 + k];
        }
        __syncthreads();

        if (act) {
            for (int ky = 0; ky < 5; ky++) {
                float iv[10];
                const float* rp = &s_in[(oy + ky) * 10];
                #pragma unroll
                for (int j = 0; j < 10; j++) iv[j] = rp[j];
                const float* wp = &s_w[oc * 25 + ky * 5];
                #pragma unroll
                for (int kx = 0; kx < 5; kx++) {
                    const float wv = wp[kx];
                    #pragma unroll
                    for (int q = 0; q < 6; q++) acc[q] = fmaf(iv[q + kx], wv, acc[q]);
                }
            }
        }
    }

    __syncthreads();
    if (act) {
        #pragma unroll
        for (int q = 0; q < 6; q++)
            s_h[oc * 36 + oy * 6 + q] = fmaxf(acc[q], 0.0f);
    }
    __syncthreads();

    // FC: each thread accumulates strided partials for all 10 outputs.
    float a[10];
    #pragma unroll
    for (int o = 0; o < 10; o++) a[o] = 0.0f;
    for (int j = tid; j < 720; j += 128) {
        const float v = s_h[j];
        #pragma unroll
        for (int o = 0; o < 10; o++) a[o] = fmaf(v, s_wf[o * 720 + j], a[o]);
    }
    #pragma unroll
    for (int o = 0; o < 10; o++) {
        float v = a[o];
        #pragma unroll
        for (int s = 16; s > 0; s >>= 1) v += __shfl_down_sync(0xffffffffu, v, s);
        if ((tid & 31) == 0) s_red[(tid >> 5) * 10 + o] = v;
    }
    __syncthreads();
    if (tid < 10) {
        const float r = __ldg(&bf[tid]) + s_red[tid] + s_red[10 + tid]
                      + s_red[20 + tid] + s_red[30 + tid];
        out[(size_t)img * 10 + tid] = r;
    }
}

// ---------------------------------------------------------------------------
extern "C" void kernel_launch(void* const* d_in, const int* in_sizes, int n_in,
                              void* d_out, int out_size)
{
    (void)in_sizes; (void)n_in; (void)out_size;
    const float* x  = (const float*)d_in[0];
    const float* w1 = (const float*)d_in[1];
    const float* b1 = (const float*)d_in[2];
    const float* w2 = (const float*)d_in[3];
    const float* b2 = (const float*)d_in[4];
    const float* w3 = (const float*)d_in[5];
    const float* b3 = (const float*)d_in[6];
    const float* wf = (const float*)d_in[7];
    const float* bf = (const float*)d_in[8];
    float* out = (float*)d_out;

    conv1_kernel<<<BATCH, 192>>>(x, w1, b1);
    conv2_kernel<<<BATCH, 128>>>(w2, b2);
    conv3_fc_kernel<<<BATCH, 128>>>(w3, b3, wf, bf, out);
}

// round 2
// speedup vs baseline: 1.0331x; 1.0331x over previous
#include <cuda_runtime.h>
#include <math.h>

#define BATCH 4096

typedef unsigned long long u64;

// Packed fp32x2 helpers (sm_103a dual-issue fp32 path; ptxas never emits
// FFMA2 from C++, only via PTX fma.rn.f32x2).
__device__ __forceinline__ u64 pack2(float lo, float hi) {
    u64 r; asm("mov.b64 %0, {%1, %2};" : "=l"(r) : "f"(lo), "f"(hi)); return r;
}
__device__ __forceinline__ u64 fma2(u64 a, u64 b, u64 c) {
    u64 d; asm("fma.rn.f32x2 %0, %1, %2, %3;" : "=l"(d) : "l"(a), "l"(b), "l"(c));
    return d;
}
__device__ __forceinline__ void unpack2(u64 v, float& lo, float& hi) {
    asm("mov.b64 {%0, %1}, %2;" : "=f"(lo), "=f"(hi) : "l"(v));
}

// Intermediate activation scratch (allocation-free: __device__ globals).
__device__ float g_h1[(size_t)BATCH * 10 * 19 * 19];   // ~59 MB
__device__ float g_h2[(size_t)BATCH * 20 * 10 * 10];   // ~33 MB

// ---------------------------------------------------------------------------
// conv1: in [1,28,28] -> relu -> out [10,19,19], kernel 10x10
// One block per image, 96 threads. Thread = (oc-pair ocg 0..4, oy 0..18),
// 95 active. Input duplicated in smem as (v,v) u64; weights pre-packed as
// (w_oc0,w_oc1) u64. Two q-passes (0..9, 10..18) to bound registers.
// ---------------------------------------------------------------------------
__global__ __launch_bounds__(96) void conv1_kernel(
    const float* __restrict__ x, const float* __restrict__ w1,
    const float* __restrict__ b1)
{
    __shared__ u64 s_in2[784];     // 28*28 duplicated
    __shared__ u64 s_w2[500];      // [ocg*100 + k] = (w[2g][k], w[2g+1][k])
    const int img = blockIdx.x;
    const int tid = threadIdx.x;

    const float* xin = x + (size_t)img * 784;
    for (int i = tid; i < 784; i += 96) { float v = xin[i]; s_in2[i] = pack2(v, v); }
    for (int i = tid; i < 500; i += 96) {
        const int g = i / 100, k = i % 100;
        s_w2[i] = pack2(w1[(2 * g) * 100 + k], w1[(2 * g + 1) * 100 + k]);
    }
    __syncthreads();

    if (tid < 95) {
        const int ocg = tid / 19;  // 0..4
        const int oy  = tid % 19;  // 0..18
        const u64 binit = pack2(__ldg(&b1[2 * ocg]), __ldg(&b1[2 * ocg + 1]));
        float* op0 = &g_h1[(size_t)img * 3610 + (2 * ocg) * 361 + oy * 19];

        // ---- pass A: outputs q = 0..9 (needs iv 0..18) ----
        {
            u64 acc2[10];
            #pragma unroll
            for (int q = 0; q < 10; q++) acc2[q] = binit;
            for (int ky = 0; ky < 10; ky++) {
                u64 iv2[19];
                const u64* rp = &s_in2[(oy + ky) * 28];
                #pragma unroll
                for (int j = 0; j < 19; j++) iv2[j] = rp[j];
                const u64* wp = &s_w2[ocg * 100 + ky * 10];
                #pragma unroll
                for (int kx = 0; kx < 10; kx++) {
                    const u64 wv = wp[kx];
                    #pragma unroll
                    for (int q = 0; q < 10; q++) acc2[q] = fma2(iv2[q + kx], wv, acc2[q]);
                }
            }
            #pragma unroll
            for (int q = 0; q < 10; q++) {
                float lo, hi; unpack2(acc2[q], lo, hi);
                op0[q]       = fmaxf(lo, 0.0f);
                op0[361 + q] = fmaxf(hi, 0.0f);
            }
        }
        // ---- pass B: outputs q = 10..18 (needs iv 10..27) ----
        {
            u64 acc2[9];
            #pragma unroll
            for (int q = 0; q < 9; q++) acc2[q] = binit;
            for (int ky = 0; ky < 10; ky++) {
                u64 iv2[18];
                const u64* rp = &s_in2[(oy + ky) * 28 + 10];
                #pragma unroll
                for (int j = 0; j < 18; j++) iv2[j] = rp[j];
                const u64* wp = &s_w2[ocg * 100 + ky * 10];
                #pragma unroll
                for (int kx = 0; kx < 10; kx++) {
                    const u64 wv = wp[kx];
                    #pragma unroll
                    for (int q = 0; q < 9; q++) acc2[q] = fma2(iv2[q + kx], wv, acc2[q]);
                }
            }
            #pragma unroll
            for (int q = 0; q < 9; q++) {
                float lo, hi; unpack2(acc2[q], lo, hi);
                op0[10 + q]       = fmaxf(lo, 0.0f);
                op0[371 + q]      = fmaxf(hi, 0.0f);
            }
        }
    }
}

// ---------------------------------------------------------------------------
// conv2: in [10,19,19] -> relu -> out [20,10,10], kernel 10x10
// One block per image, 128 threads, 100 active. Thread = (ocg 0..9, oy 0..9),
// 2 output channels per thread packed in f32x2 accumulators.
// Input plane duplicated (v,v); weights packed (w_oc0,w_oc1).
// iv2 LDS.64 loads verified conflict-free (stride 38 words -> banks 6*oy mod 32).
// ---------------------------------------------------------------------------
__global__ __launch_bounds__(128) void conv2_kernel(
    const float* __restrict__ w2, const float* __restrict__ b2)
{
    __shared__ u64 s_in2[361];     // 19*19 duplicated, one input channel
    __shared__ u64 s_w2[1000];     // [ocg*100 + ky*10 + kx] packed oc pair
    const int img = blockIdx.x;
    const int tid = threadIdx.x;
    const bool act = tid < 100;
    const int ocg = tid / 10;      // 0..9
    const int oy  = tid % 10;

    u64 acc2[10];
    if (act) {
        const u64 binit = pack2(__ldg(&b2[2 * ocg]), __ldg(&b2[2 * ocg + 1]));
        #pragma unroll
        for (int q = 0; q < 10; q++) acc2[q] = binit;
    }

    const float* h1p = g_h1 + (size_t)img * 3610;
    for (int c = 0; c < 10; c++) {
        __syncthreads();
        for (int i = tid; i < 361; i += 128) {
            const float v = h1p[c * 361 + i];
            s_in2[i] = pack2(v, v);
        }
        for (int i = tid; i < 1000; i += 128) {
            const int g = i / 100, k = i % 100;
            s_w2[i] = pack2(w2[(2 * g) * 1000 + c * 100 + k],
                            w2[(2 * g + 1) * 1000 + c * 100 + k]);
        }
        __syncthreads();

        if (act) {
            for (int ky = 0; ky < 10; ky++) {
                u64 iv2[19];
                const u64* rp = &s_in2[(oy + ky) * 19];
                #pragma unroll
                for (int j = 0; j < 19; j++) iv2[j] = rp[j];
                const u64* wp = &s_w2[ocg * 100 + ky * 10];
                #pragma unroll
                for (int kx = 0; kx < 10; kx++) {
                    const u64 wv = wp[kx];
                    #pragma unroll
                    for (int q = 0; q < 10; q++) acc2[q] = fma2(iv2[q + kx], wv, acc2[q]);
                }
            }
        }
    }

    if (act) {
        float* op = g_h2 + (size_t)img * 2000 + (2 * ocg) * 100 + oy * 10;
        #pragma unroll
        for (int q = 0; q < 10; q++) {
            float lo, hi; unpack2(acc2[q], lo, hi);
            op[q]       = fmaxf(lo, 0.0f);
            op[100 + q] = fmaxf(hi, 0.0f);
        }
    }
}

// ---------------------------------------------------------------------------
// conv3 + FC: in [20,10,10] -> relu conv [20,6,6] (k5) -> flatten 720
//             -> out[10] = h @ wf^T + bf
// One block per image, 128 threads. Conv thread = (ocg 0..9, oy 0..5),
// 60 active, f32x2 oc-pair packing. FC by all 128 threads + warp reduction.
// ---------------------------------------------------------------------------
__global__ __launch_bounds__(128) void conv3_fc_kernel(
    const float* __restrict__ w3, const float* __restrict__ b3,
    const float* __restrict__ wf, const float* __restrict__ bf,
    float* __restrict__ out)
{
    __shared__ u64 s_in2[100];     // 10x10 duplicated, one input channel
    __shared__ u64 s_w2[250];      // [ocg*25 + ky*5 + kx] packed oc pair
    __shared__ float s_h[720];     // conv3 relu output (oc*36 + oy*6 + ox)
    __shared__ float s_wf[7200];   // FC weights [10][720]
    __shared__ float s_red[40];    // per-warp FC partials

    const int img = blockIdx.x;
    const int tid = threadIdx.x;

    for (int i = tid; i < 7200; i += 128) s_wf[i] = wf[i];

    const bool act = tid < 60;
    const int ocg = tid / 6;       // 0..9
    const int oy  = tid % 6;
    u64 acc2[6];
    if (act) {
        const u64 binit = pack2(__ldg(&b3[2 * ocg]), __ldg(&b3[2 * ocg + 1]));
        #pragma unroll
        for (int q = 0; q < 6; q++) acc2[q] = binit;
    }

    const float* h2p = g_h2 + (size_t)img * 2000;
    for (int c = 0; c < 20; c++) {
        __syncthreads();
        if (tid < 100) { const float v = h2p[c * 100 + tid]; s_in2[tid] = pack2(v, v); }
        for (int i = tid; i < 250; i += 128) {
            const int g = i / 25, k = i % 25;
            s_w2[i] = pack2(w3[(2 * g) * 500 + c * 25 + k],
                            w3[(2 * g + 1) * 500 + c * 25 + k]);
        }
        __syncthreads();

        if (act) {
            for (int ky = 0; ky < 5; ky++) {
                u64 iv2[10];
                const u64* rp = &s_in2[(oy + ky) * 10];
                #pragma unroll
                for (int j = 0; j < 10; j++) iv2[j] = rp[j];
                const u64* wp = &s_w2[ocg * 25 + ky * 5];
                #pragma unroll
                for (int kx = 0; kx < 5; kx++) {
                    const u64 wv = wp[kx];
                    #pragma unroll
                    for (int q = 0; q < 6; q++) acc2[q] = fma2(iv2[q + kx], wv, acc2[q]);
                }
            }
        }
    }

    __syncthreads();
    if (act) {
        #pragma unroll
        for (int q = 0; q < 6; q++) {
            float lo, hi; unpack2(acc2[q], lo, hi);
            s_h[(2 * ocg) * 36 + oy * 6 + q]     = fmaxf(lo, 0.0f);
            s_h[(2 * ocg + 1) * 36 + oy * 6 + q] = fmaxf(hi, 0.0f);
        }
    }
    __syncthreads();

    // FC: each thread accumulates strided partials for all 10 outputs.
    float a[10];
    #pragma unroll
    for (int o = 0; o < 10; o++) a[o] = 0.0f;
    for (int j = tid; j < 720; j += 128) {
        const float v = s_h[j];
        #pragma unroll
        for (int o = 0; o < 10; o++) a[o] = fmaf(v, s_wf[o * 720 + j], a[o]);
    }
    #pragma unroll
    for (int o = 0; o < 10; o++) {
        float v = a[o];
        #pragma unroll
        for (int s = 16; s > 0; s >>= 1) v += __shfl_down_sync(0xffffffffu, v, s);
        if ((tid & 31) == 0) s_red[(tid >> 5) * 10 + o] = v;
    }
    __syncthreads();
    if (tid < 10) {
        const float r = __ldg(&bf[tid]) + s_red[tid] + s_red[10 + tid]
                      + s_red[20 + tid] + s_red[30 + tid];
        out[(size_t)img * 10 + tid] = r;
    }
}

// ---------------------------------------------------------------------------
extern "C" void kernel_launch(void* const* d_in, const int* in_sizes, int n_in,
                              void* d_out, int out_size)
{
    (void)in_sizes; (void)n_in; (void)out_size;
    const float* x  = (const float*)d_in[0];
    const float* w1 = (const float*)d_in[1];
    const float* b1 = (const float*)d_in[2];
    const float* w2 = (const float*)d_in[3];
    const float* b2 = (const float*)d_in[4];
    const float* w3 = (const float*)d_in[5];
    const float* b3 = (const float*)d_in[6];
    const float* wf = (const float*)d_in[7];
    const float* bf = (const float*)d_in[8];
    float* out = (float*)d_out;

    conv1_kernel<<<BATCH, 96>>>(x, w1, b1);
    conv2_kernel<<<BATCH, 128>>>(w2, b2);
    conv3_fc_kernel<<<BATCH, 128>>>(w3, b3, wf, bf, out);
}

// round 4
// speedup vs baseline: 1.3097x; 1.2677x over previous
#include <cuda_runtime.h>
#include <math.h>

#define BATCH 4096
#define NPAIR (BATCH / 2)

typedef unsigned long long u64;

// ---- packed fp32x2 helpers (sm_103a; ptxas never emits FFMA2 from C++) ----
__device__ __forceinline__ u64 pack2(float lo, float hi) {
    u64 r; asm("mov.b64 %0, {%1, %2};" : "=l"(r) : "f"(lo), "f"(hi)); return r;
}
__device__ __forceinline__ u64 fma2(u64 a, u64 b, u64 c) {
    u64 d; asm("fma.rn.f32x2 %0, %1, %2, %3;" : "=l"(d) : "l"(a), "l"(b), "l"(c));
    return d;
}
__device__ __forceinline__ void unpack2(u64 v, float& lo, float& hi) {
    asm("mov.b64 {%0, %1}, %2;" : "=f"(lo), "=f"(hi) : "l"(v));
}
__device__ __forceinline__ u64 relu2(u64 v) {
    float lo, hi; unpack2(v, lo, hi);
    return pack2(fmaxf(lo, 0.0f), fmaxf(hi, 0.0f));
}

// Paired-image intermediates: element [pair][...] = (img 2p value, img 2p+1 value)
__device__ u64 g_h1_2[(size_t)NPAIR * 10 * 361];   // conv1 out, [pair][oc][oy*19+ox]
__device__ u64 g_h2_2[(size_t)NPAIR * 20 * 100];   // conv2 out, [pair][oc][oy*10+ox]

// ---------------------------------------------------------------------------
// conv1: [1,28,28] -> relu -> [10,19,19], k10. One block per image PAIR.
// 96 threads, 95 active: thread = (ocg 0..4 [2 oc], oy 0..18).
// Input pitch 29 u64 (conflict-free: 13*row mod 16, gcd=1).
// Two q-passes (0..9, 10..18) to bound registers.
// ---------------------------------------------------------------------------
__global__ __launch_bounds__(96) void conv1_kernel(
    const float* __restrict__ x, const float* __restrict__ w1,
    const float* __restrict__ b1)
{
    __shared__ u64 s_in2[28 * 29];   // pitch-padded
    __shared__ u64 s_w2[1000];       // [oc*100 + k] = (w,w)
    const int bid = blockIdx.x;
    const int tid = threadIdx.x;

    const float* x0 = x + (size_t)(2 * bid) * 784;
    const float* x1 = x0 + 784;
    for (int i = tid; i < 784; i += 96) {
        const int r = i / 28, c = i % 28;
        s_in2[r * 29 + c] = pack2(x0[i], x1[i]);
    }
    for (int i = tid; i < 1000; i += 96) {
        const float w = w1[i];
        s_w2[i] = pack2(w, w);
    }
    __syncthreads();

    if (tid < 95) {
        const int ocg = tid / 19, oy = tid % 19;
        const int oc0 = 2 * ocg;
        const float bv0 = __ldg(&b1[oc0]), bv1 = __ldg(&b1[oc0 + 1]);
        const u64 bi0 = pack2(bv0, bv0), bi1 = pack2(bv1, bv1);
        u64* op0 = &g_h1_2[((size_t)bid * 10 + oc0) * 361 + oy * 19];

        // pass A: outputs q = 0..9
        {
            u64 a0[10], a1[10];
            #pragma unroll
            for (int q = 0; q < 10; q++) { a0[q] = bi0; a1[q] = bi1; }
            for (int ky = 0; ky < 10; ky++) {
                u64 iv[19];
                const u64* rp = &s_in2[(oy + ky) * 29];
                #pragma unroll
                for (int j = 0; j < 19; j++) iv[j] = rp[j];
                const u64* wp0 = &s_w2[oc0 * 100 + ky * 10];
                const u64* wp1 = wp0 + 100;
                #pragma unroll
                for (int kx = 0; kx < 10; kx++) {
                    const u64 w0 = wp0[kx], w1v = wp1[kx];
                    #pragma unroll
                    for (int q = 0; q < 10; q++) {
                        a0[q] = fma2(iv[q + kx], w0, a0[q]);
                        a1[q] = fma2(iv[q + kx], w1v, a1[q]);
                    }
                }
            }
            #pragma unroll
            for (int q = 0; q < 10; q++) {
                op0[q]       = relu2(a0[q]);
                op0[361 + q] = relu2(a1[q]);
            }
        }
        // pass B: outputs q = 10..18
        {
            u64 a0[9], a1[9];
            #pragma unroll
            for (int q = 0; q < 9; q++) { a0[q] = bi0; a1[q] = bi1; }
            for (int ky = 0; ky < 10; ky++) {
                u64 iv[18];
                const u64* rp = &s_in2[(oy + ky) * 29 + 10];
                #pragma unroll
                for (int j = 0; j < 18; j++) iv[j] = rp[j];
                const u64* wp0 = &s_w2[oc0 * 100 + ky * 10];
                const u64* wp1 = wp0 + 100;
                #pragma unroll
                for (int kx = 0; kx < 10; kx++) {
                    const u64 w0 = wp0[kx], w1v = wp1[kx];
                    #pragma unroll
                    for (int q = 0; q < 9; q++) {
                        a0[q] = fma2(iv[q + kx], w0, a0[q]);
                        a1[q] = fma2(iv[q + kx], w1v, a1[q]);
                    }
                }
            }
            #pragma unroll
            for (int q = 0; q < 9; q++) {
                op0[10 + q]  = relu2(a0[q]);
                op0[371 + q] = relu2(a1[q]);
            }
        }
    }
}

// ---------------------------------------------------------------------------
// conv2: [10,19,19] -> relu -> [20,10,10], k10. One block per image PAIR.
// 128 threads, 100 active: thread = (ocg 0..9 [2 oc], oy 0..9).
// Input pitch 19 (conflict-free: 3*row mod 16), weight pitch 101.
// ---------------------------------------------------------------------------
__global__ __launch_bounds__(128) void conv2_kernel(
    const float* __restrict__ w2, const float* __restrict__ b2)
{
    __shared__ u64 s_in2[361];
    __shared__ u64 s_w2[2020];      // [oc*101 + k] = (w,w)
    const int bid = blockIdx.x;
    const int tid = threadIdx.x;
    const bool act = tid < 100;
    const int ocg = tid / 10, oy = tid % 10;
    const int oc0 = 2 * ocg;

    u64 a0[10], a1[10];
    if (act) {
        const float bv0 = __ldg(&b2[oc0]), bv1 = __ldg(&b2[oc0 + 1]);
        const u64 bi0 = pack2(bv0, bv0), bi1 = pack2(bv1, bv1);
        #pragma unroll
        for (int q = 0; q < 10; q++) { a0[q] = bi0; a1[q] = bi1; }
    }

    const u64* h1p = &g_h1_2[(size_t)bid * 3610];
    for (int c = 0; c < 10; c++) {
        __syncthreads();
        for (int i = tid; i < 361; i += 128) s_in2[i] = h1p[c * 361 + i];
        for (int i = tid; i < 2000; i += 128) {
            const int oc = i / 100, k = i % 100;
            const float w = w2[oc * 1000 + c * 100 + k];
            s_w2[oc * 101 + k] = pack2(w, w);
        }
        __syncthreads();

        if (act) {
            for (int ky = 0; ky < 10; ky++) {
                u64 iv[19];
                const u64* rp = &s_in2[(oy + ky) * 19];
                #pragma unroll
                for (int j = 0; j < 19; j++) iv[j] = rp[j];
                const u64* wp0 = &s_w2[oc0 * 101 + ky * 10];
                const u64* wp1 = wp0 + 101;
                #pragma unroll
                for (int kx = 0; kx < 10; kx++) {
                    const u64 w0 = wp0[kx], w1v = wp1[kx];
                    #pragma unroll
                    for (int q = 0; q < 10; q++) {
                        a0[q] = fma2(iv[q + kx], w0, a0[q]);
                        a1[q] = fma2(iv[q + kx], w1v, a1[q]);
                    }
                }
            }
        }
    }

    if (act) {
        u64* op = &g_h2_2[((size_t)bid * 20 + oc0) * 100 + oy * 10];
        #pragma unroll
        for (int q = 0; q < 10; q++) {
            op[q]       = relu2(a0[q]);
            op[100 + q] = relu2(a1[q]);
        }
    }
}

// ---------------------------------------------------------------------------
// conv3 + FC: [20,10,10] -> relu conv [20,6,6] (k5) -> 720 -> out[10].
// One block per 2 image pairs (4 images), 128 threads.
// Conv: 120 active, thread = (pp 0..1, ocg 0..9 [2 oc], oy 0..5).
// Input pitch 11 (11*row mod 16, gcd=1 -> conflict-free).
// FC: all 128 threads, pair pp = tid>>6, strided j, f32x2 over the pair.
// ---------------------------------------------------------------------------
__global__ __launch_bounds__(128) void conv3_fc_kernel(
    const float* __restrict__ w3, const float* __restrict__ b3,
    const float* __restrict__ wf, const float* __restrict__ bf,
    float* __restrict__ out)
{
    __shared__ u64 s_in2[2][110];    // pitch 11
    __shared__ u64 s_w2[500];        // [oc*25 + k] = (w,w)
    __shared__ u64 s_h2[2][720];     // conv3 relu out per pair (20 oc * 36)
    __shared__ float s_rlo[4][10], s_rhi[4][10];

    const int bid = blockIdx.x;      // covers pairs 2*bid, 2*bid+1
    const int tid = threadIdx.x;
    const int p0 = 2 * bid;

    const bool act = tid < 120;
    const int pp  = tid / 60;
    const int r   = tid % 60;
    const int ocg = r / 6, oy = r % 6;
    const int oc0 = 2 * ocg;

    u64 a0[6], a1[6];
    if (act) {
        const float bv0 = __ldg(&b3[oc0]), bv1 = __ldg(&b3[oc0 + 1]);
        const u64 bi0 = pack2(bv0, bv0), bi1 = pack2(bv1, bv1);
        #pragma unroll
        for (int q = 0; q < 6; q++) { a0[q] = bi0; a1[q] = bi1; }
    }

    for (int c = 0; c < 20; c++) {
        __syncthreads();
        for (int i = tid; i < 200; i += 128) {
            const int pq = i / 100, j = i % 100;
            s_in2[pq][(j / 10) * 11 + (j % 10)] =
                g_h2_2[((size_t)(p0 + pq) * 20 + c) * 100 + j];
        }
        for (int i = tid; i < 500; i += 128) {
            const int oc = i / 25, k = i % 25;
            const float w = w3[oc * 500 + c * 25 + k];
            s_w2[i] = pack2(w, w);
        }
        __syncthreads();

        if (act) {
            for (int ky = 0; ky < 5; ky++) {
                u64 iv[10];
                const u64* rp = &s_in2[pp][(oy + ky) * 11];
                #pragma unroll
                for (int j = 0; j < 10; j++) iv[j] = rp[j];
                const u64* wp0 = &s_w2[oc0 * 25 + ky * 5];
                const u64* wp1 = wp0 + 25;
                #pragma unroll
                for (int kx = 0; kx < 5; kx++) {
                    const u64 w0 = wp0[kx], w1v = wp1[kx];
                    #pragma unroll
                    for (int q = 0; q < 6; q++) {
                        a0[q] = fma2(iv[q + kx], w0, a0[q]);
                        a1[q] = fma2(iv[q + kx], w1v, a1[q]);
                    }
                }
            }
        }
    }

    __syncthreads();
    if (act) {
        #pragma unroll
        for (int q = 0; q < 6; q++) {
            s_h2[pp][oc0 * 36 + oy * 6 + q]       = relu2(a0[q]);
            s_h2[pp][(oc0 + 1) * 36 + oy * 6 + q] = relu2(a1[q]);
        }
    }
    __syncthreads();

    // ---- FC over the pair: threads 0-63 -> pair p0, 64-127 -> pair p0+1 ----
    {
        const int fpp = tid >> 6;
        const int j0  = tid & 63;
        u64 acc[10];
        #pragma unroll
        for (int o = 0; o < 10; o++) acc[o] = 0ULL;
        for (int j = j0; j < 720; j += 64) {
            const u64 v2 = s_h2[fpp][j];
            #pragma unroll
            for (int o = 0; o < 10; o++) {
                const float w = __ldg(&wf[o * 720 + j]);
                acc[o] = fma2(v2, pack2(w, w), acc[o]);
            }
        }
        const int wid = tid >> 5;
        #pragma unroll
        for (int o = 0; o < 10; o++) {
            float lo, hi; unpack2(acc[o], lo, hi);
            #pragma unroll
            for (int s = 16; s > 0; s >>= 1) {
                lo += __shfl_down_sync(0xffffffffu, lo, s);
                hi += __shfl_down_sync(0xffffffffu, hi, s);
            }
            if ((tid & 31) == 0) { s_rlo[wid][o] = lo; s_rhi[wid][o] = hi; }
        }
    }
    __syncthreads();
    if (tid < 40) {
        const int o  = tid % 10;
        const int im = tid / 10;          // 0..3 -> image 4*bid + im
        const int fpp  = im >> 1;         // which pair
        const int half = im & 1;          // lo = img 2p, hi = img 2p+1
        const int w0 = 2 * fpp;
        float v;
        if (half == 0) v = s_rlo[w0][o] + s_rlo[w0 + 1][o];
        else           v = s_rhi[w0][o] + s_rhi[w0 + 1][o];
        out[(size_t)(4 * bid + im) * 10 + o] = v + __ldg(&bf[o]);
    }
}

// ---------------------------------------------------------------------------
extern "C" void kernel_launch(void* const* d_in, const int* in_sizes, int n_in,
                              void* d_out, int out_size)
{
    (void)in_sizes; (void)n_in; (void)out_size;
    const float* x  = (const float*)d_in[0];
    const float* w1 = (const float*)d_in[1];
    const float* b1 = (const float*)d_in[2];
    const float* w2 = (const float*)d_in[3];
    const float* b2 = (const float*)d_in[4];
    const float* w3 = (const float*)d_in[5];
    const float* b3 = (const float*)d_in[6];
    const float* wf = (const float*)d_in[7];
    const float* bf = (const float*)d_in[8];
    float* out = (float*)d_out;

    conv1_kernel<<<NPAIR, 96>>>(x, w1, b1);
    conv2_kernel<<<NPAIR, 128>>>(w2, b2);
    conv3_fc_kernel<<<NPAIR / 2, 128>>>(w3, b3, wf, bf, out);
}